// round 5
// baseline (speedup 1.0000x reference)
#include <cuda_runtime.h>
#include <cuda_bf16.h>

// GANLoss: out = -mean(prob[n, targets[n]] * reward[n]), N=8192, C=32000.
// Single graph node: one CTA, 1024 threads x 8 rows each. Deterministic
// in-block tree reduction, direct store (no atomics, no memset node).
// Across graph replays the 8192 gathered lines (~1MB) are L2-resident,
// so this is ~one L2 round trip of real work; node overhead dominates.

#define NTHREADS 1024
#define ROWS_PER_THREAD 8   // N = 8192 = 1024 * 8

__global__ __launch_bounds__(NTHREADS) void ganloss_kernel(
    const float* __restrict__ prob,
    const int* __restrict__ targets,
    const float* __restrict__ reward,
    float* __restrict__ out,
    long long C, float neg_inv_n)
{
    const int tid = threadIdx.x;

    // Load targets + rewards first (coalesced, stride-NTHREADS), then issue
    // all 8 gathers back-to-back so each thread has MLP=8 on the gather.
    int   t[ROWS_PER_THREAD];
    float r[ROWS_PER_THREAD];
    #pragma unroll
    for (int i = 0; i < ROWS_PER_THREAD; i++) {
        int row = tid + i * NTHREADS;
        t[i] = __ldg(&targets[row]);
        r[i] = __ldg(&reward[row]);
    }

    float p[ROWS_PER_THREAD];
    #pragma unroll
    for (int i = 0; i < ROWS_PER_THREAD; i++) {
        long long row = (long long)(tid + i * NTHREADS);
        p[i] = __ldg(&prob[row * C + (long long)t[i]]);
    }

    float v = 0.0f;
    #pragma unroll
    for (int i = 0; i < ROWS_PER_THREAD; i++)
        v = fmaf(p[i], r[i], v);

    // warp reduce
    #pragma unroll
    for (int off = 16; off > 0; off >>= 1)
        v += __shfl_xor_sync(0xFFFFFFFFu, v, off);

    __shared__ float s_warp[NTHREADS / 32];
    const int lane = tid & 31;
    const int wid  = tid >> 5;
    if (lane == 0) s_warp[wid] = v;
    __syncthreads();

    if (wid == 0) {
        float w = s_warp[lane];   // exactly 32 partials
        #pragma unroll
        for (int off = 16; off > 0; off >>= 1)
            w += __shfl_xor_sync(0xFFFFFFFFu, w, off);
        if (lane == 0)
            out[0] = w * neg_inv_n;
    }
}

extern "C" void kernel_launch(void* const* d_in, const int* in_sizes, int n_in,
                              void* d_out, int out_size)
{
    const float* prob    = (const float*)d_in[0];
    const int*   targets = (const int*)d_in[1];
    const float* reward  = (const float*)d_in[2];
    float*       out     = (float*)d_out;

    const int N = in_sizes[2];                       // 8192
    const long long C = (long long)in_sizes[0] / N;  // 32000

    ganloss_kernel<<<1, NTHREADS>>>(prob, targets, reward, out,
                                    C, -1.0f / (float)N);
}

// round 6
// speedup vs baseline: 1.3042x; 1.3042x over previous
#include <cuda_runtime.h>
#include <cuda_bf16.h>

// GANLoss: out = -mean(prob[n, targets[n]] * reward[n]), N=8192, C=32000.
// ONE kernel node, no memset, no membars. Per-warp release-red.add into a
// device accumulator; acq_rel counter atomic detects the last warp, which
// acquire-loads the total, writes out, and resets scratch for graph replay.

#define NBLOCKS  32
#define NTHREADS 256
#define TOTAL_WARPS (NBLOCKS * NTHREADS / 32)   // 256

__device__ float g_accum = 0.0f;
__device__ int   g_count = 0;

__global__ __launch_bounds__(NTHREADS) void ganloss_kernel(
    const float* __restrict__ prob,
    const int* __restrict__ targets,
    const float* __restrict__ reward,
    float* __restrict__ out,
    int N, long long C, float neg_inv_n)
{
    int idx = blockIdx.x * blockDim.x + threadIdx.x;

    float v = 0.0f;
    if (idx < N) {
        int t = targets[idx];
        v = __ldg(&prob[(long long)idx * C + (long long)t]) * __ldg(&reward[idx]);
    }
    v *= neg_inv_n;

    // warp reduce (5 shuffles)
    #pragma unroll
    for (int off = 16; off > 0; off >>= 1)
        v += __shfl_xor_sync(0xFFFFFFFFu, v, off);

    if ((threadIdx.x & 31) == 0) {
        // release-ordered no-return float add into the accumulator
        asm volatile("red.release.gpu.add.f32 [%0], %1;"
                     :: "l"(&g_accum), "f"(v) : "memory");

        // acq_rel counter: total order on this address; acquiring the RMW
        // chain makes every warp's prior release-add visible to the last one.
        int old;
        asm volatile("atom.acq_rel.gpu.add.s32 %0, [%1], %2;"
                     : "=r"(old) : "l"(&g_count), "r"(1) : "memory");

        if (old == TOTAL_WARPS - 1) {
            float s;
            asm volatile("ld.acquire.gpu.f32 %0, [%1];"
                         : "=f"(s) : "l"(&g_accum) : "memory");
            out[0] = s;
            // reset scratch for the next graph replay (kernel-boundary
            // ordering makes these visible to the next launch)
            g_accum = 0.0f;
            g_count = 0;
        }
    }
}

extern "C" void kernel_launch(void* const* d_in, const int* in_sizes, int n_in,
                              void* d_out, int out_size)
{
    const float* prob    = (const float*)d_in[0];
    const int*   targets = (const int*)d_in[1];
    const float* reward  = (const float*)d_in[2];
    float*       out     = (float*)d_out;

    const int N = in_sizes[2];                       // 8192
    const long long C = (long long)in_sizes[0] / N;  // 32000

    ganloss_kernel<<<NBLOCKS, NTHREADS>>>(prob, targets, reward, out,
                                          N, C, -1.0f / (float)N);
}

// round 7
// speedup vs baseline: 1.4115x; 1.0823x over previous
#include <cuda_runtime.h>
#include <cuda_bf16.h>

// GANLoss: out = -mean(prob[n, targets[n]] * reward[n]), N=8192, C=32000.
// Two graph nodes: 4-byte memset zeroes out[0]; gather kernel reduces each
// block fully in smem/shuffles and fires exactly ONE no-return float
// atomicAdd (REDG) per block, pre-scaled by -1/N. Only 32 same-address
// L2 RMWs total (vs 256 in R4, 512 in R6) -> tail ~0.5us.

#define NBLOCKS  32
#define NTHREADS 256

__global__ __launch_bounds__(NTHREADS) void ganloss_kernel(
    const float* __restrict__ prob,
    const int* __restrict__ targets,
    const float* __restrict__ reward,
    float* __restrict__ out,
    int N, long long C, float neg_inv_n)
{
    int idx = blockIdx.x * blockDim.x + threadIdx.x;

    float v = 0.0f;
    if (idx < N) {
        int t = targets[idx];
        v = __ldg(&prob[(long long)idx * C + (long long)t]) * __ldg(&reward[idx]);
    }

    // warp reduce (5 shuffles)
    #pragma unroll
    for (int off = 16; off > 0; off >>= 1)
        v += __shfl_xor_sync(0xFFFFFFFFu, v, off);

    __shared__ float s_warp[NTHREADS / 32];
    const int lane = threadIdx.x & 31;
    const int wid  = threadIdx.x >> 5;
    if (lane == 0) s_warp[wid] = v;
    __syncthreads();

    if (wid == 0) {
        float w = (lane < NTHREADS / 32) ? s_warp[lane] : 0.0f;
        #pragma unroll
        for (int off = 4; off > 0; off >>= 1)
            w += __shfl_xor_sync(0xFFFFFFFFu, w, off);
        // ONE no-return atomic per block (REDG), pre-scaled
        if (lane == 0)
            atomicAdd(out, w * neg_inv_n);
    }
}

extern "C" void kernel_launch(void* const* d_in, const int* in_sizes, int n_in,
                              void* d_out, int out_size)
{
    const float* prob    = (const float*)d_in[0];
    const int*   targets = (const int*)d_in[1];
    const float* reward  = (const float*)d_in[2];
    float*       out     = (float*)d_out;

    const int N = in_sizes[2];                       // 8192
    const long long C = (long long)in_sizes[0] / N;  // 32000

    cudaMemsetAsync(out, 0, sizeof(float));
    ganloss_kernel<<<NBLOCKS, NTHREADS>>>(prob, targets, reward, out,
                                          N, C, -1.0f / (float)N);
}

// round 8
// speedup vs baseline: 1.5880x; 1.1250x over previous
#include <cuda_runtime.h>
#include <cuda_bf16.h>

// GANLoss: out = -mean(prob[n, targets[n]] * reward[n]), N=8192, C=32000.
// Two kernels (best structure so far: R2 @ 6.94us), but the finalize is
// launched with Programmatic Dependent Launch so its launch setup overlaps
// the gather kernel's execution (DeepGEMM epilogue pattern). Deterministic
// fixed-order reduction, no atomics, no memset node.

#define NBLOCKS  64
#define NTHREADS 128

__device__ float g_partials[NBLOCKS];

__global__ __launch_bounds__(NTHREADS) void gather_kernel(
    const float* __restrict__ prob,
    const int* __restrict__ targets,
    const float* __restrict__ reward,
    int N, long long C)
{
    int idx = blockIdx.x * blockDim.x + threadIdx.x;

    float v = 0.0f;
    if (idx < N) {
        int t = targets[idx];
        v = __ldg(&prob[(long long)idx * C + (long long)t]) * __ldg(&reward[idx]);
    }

    // warp reduce (5 shuffles)
    #pragma unroll
    for (int off = 16; off > 0; off >>= 1)
        v += __shfl_xor_sync(0xFFFFFFFFu, v, off);

    __shared__ float s_warp[NTHREADS / 32];
    const int lane = threadIdx.x & 31;
    const int wid  = threadIdx.x >> 5;
    if (lane == 0) s_warp[wid] = v;
    __syncthreads();

    if (threadIdx.x < 32) {
        float w = (lane < NTHREADS / 32) ? s_warp[lane] : 0.0f;
        #pragma unroll
        for (int off = 2; off > 0; off >>= 1)
            w += __shfl_xor_sync(0xFFFFFFFFu, w, off);
        if (lane == 0) g_partials[blockIdx.x] = w;
    }
}

__global__ __launch_bounds__(64) void finalize_kernel(
    float* __restrict__ out, float neg_inv_n)
{
    // Wait for the primary grid (PDL edge): guarantees g_partials visible.
    cudaGridDependencySynchronize();

    float v = g_partials[threadIdx.x];          // 64 partials, 2 warps
    #pragma unroll
    for (int off = 16; off > 0; off >>= 1)
        v += __shfl_xor_sync(0xFFFFFFFFu, v, off);

    __shared__ float s2[2];
    if ((threadIdx.x & 31) == 0) s2[threadIdx.x >> 5] = v;
    __syncthreads();

    if (threadIdx.x == 0)
        out[0] = (s2[0] + s2[1]) * neg_inv_n;
}

extern "C" void kernel_launch(void* const* d_in, const int* in_sizes, int n_in,
                              void* d_out, int out_size)
{
    const float* prob    = (const float*)d_in[0];
    const int*   targets = (const int*)d_in[1];
    const float* reward  = (const float*)d_in[2];
    float*       out     = (float*)d_out;

    const int N = in_sizes[2];                       // 8192
    const long long C = (long long)in_sizes[0] / N;  // 32000

    gather_kernel<<<NBLOCKS, NTHREADS>>>(prob, targets, reward, N, C);

    // Finalize with Programmatic Stream Serialization: launch setup overlaps
    // the gather's execution; the device-side griddepcontrol.wait provides
    // the actual dependency + memory visibility.
    cudaLaunchConfig_t cfg = {};
    cfg.gridDim  = dim3(1, 1, 1);
    cfg.blockDim = dim3(64, 1, 1);
    cfg.dynamicSmemBytes = 0;
    cfg.stream = 0;
    cudaLaunchAttribute attr;
    attr.id = cudaLaunchAttributeProgrammaticStreamSerialization;
    attr.val.programmaticStreamSerializationAllowed = 1;
    cfg.attrs = &attr;
    cfg.numAttrs = 1;

    float neg_inv_n = -1.0f / (float)N;
    cudaLaunchKernelEx(&cfg, finalize_kernel, out, neg_inv_n);
}

// round 9
// speedup vs baseline: 1.6490x; 1.0385x over previous
#include <cuda_runtime.h>
#include <cuda_bf16.h>

// GANLoss: out = -mean(prob[n, targets[n]] * reward[n]), N=8192, C=32000.
// Two kernels with full PDL: gather fires cudaTriggerProgrammaticLaunchCompletion
// right after writing its block partial, so the finalize's
// cudaGridDependencySynchronize releases at trigger time (all CTAs stored),
// overlapping the gather's drain/retire with the finalize body.
// Deterministic fixed-order reduction, no atomics, no memset node.

#define NBLOCKS  32
#define NTHREADS 256

__device__ float g_partials[NBLOCKS];

__global__ __launch_bounds__(NTHREADS) void gather_kernel(
    const float* __restrict__ prob,
    const int* __restrict__ targets,
    const float* __restrict__ reward,
    int N, long long C)
{
    int idx = blockIdx.x * blockDim.x + threadIdx.x;

    float v = 0.0f;
    if (idx < N) {
        int t = targets[idx];
        v = __ldg(&prob[(long long)idx * C + (long long)t]) * __ldg(&reward[idx]);
    }

    // warp reduce (5 shuffles)
    #pragma unroll
    for (int off = 16; off > 0; off >>= 1)
        v += __shfl_xor_sync(0xFFFFFFFFu, v, off);

    __shared__ float s_warp[NTHREADS / 32];
    const int lane = threadIdx.x & 31;
    const int wid  = threadIdx.x >> 5;
    if (lane == 0) s_warp[wid] = v;
    __syncthreads();

    if (threadIdx.x < 32) {
        float w = (lane < NTHREADS / 32) ? s_warp[lane] : 0.0f;
        #pragma unroll
        for (int off = 4; off > 0; off >>= 1)
            w += __shfl_xor_sync(0xFFFFFFFFu, w, off);
        if (lane == 0) g_partials[blockIdx.x] = w;
    }

    // Release the dependent finalize grid as soon as this CTA's partial is
    // stored (pre-trigger writes are visible to the dependent grid per the
    // PDL contract). Remaining CTA teardown overlaps the finalize.
    cudaTriggerProgrammaticLaunchCompletion();
}

__global__ __launch_bounds__(32) void finalize_kernel(
    float* __restrict__ out, float neg_inv_n)
{
    // Releases when all gather CTAs have triggered (not full retire).
    cudaGridDependencySynchronize();

    float v = g_partials[threadIdx.x];          // 32 partials, 1 warp
    #pragma unroll
    for (int off = 16; off > 0; off >>= 1)
        v += __shfl_xor_sync(0xFFFFFFFFu, v, off);

    if (threadIdx.x == 0)
        out[0] = v * neg_inv_n;
}

extern "C" void kernel_launch(void* const* d_in, const int* in_sizes, int n_in,
                              void* d_out, int out_size)
{
    const float* prob    = (const float*)d_in[0];
    const int*   targets = (const int*)d_in[1];
    const float* reward  = (const float*)d_in[2];
    float*       out     = (float*)d_out;

    const int N = in_sizes[2];                       // 8192
    const long long C = (long long)in_sizes[0] / N;  // 32000

    gather_kernel<<<NBLOCKS, NTHREADS>>>(prob, targets, reward, N, C);

    cudaLaunchConfig_t cfg = {};
    cfg.gridDim  = dim3(1, 1, 1);
    cfg.blockDim = dim3(32, 1, 1);
    cfg.dynamicSmemBytes = 0;
    cfg.stream = 0;
    cudaLaunchAttribute attr;
    attr.id = cudaLaunchAttributeProgrammaticStreamSerialization;
    attr.val.programmaticStreamSerializationAllowed = 1;
    cfg.attrs = &attr;
    cfg.numAttrs = 1;

    float neg_inv_n = -1.0f / (float)N;
    cudaLaunchKernelEx(&cfg, finalize_kernel, out, neg_inv_n);
}

// round 10
// speedup vs baseline: 1.6650x; 1.0097x over previous
#include <cuda_runtime.h>
#include <cuda_bf16.h>

// GANLoss: out = -mean(prob[n, targets[n]] * reward[n]), N=8192, C=32000.
// Full-overlap PDL: gather triggers launch-completion at ENTRY, so the
// finalize block is resident while the gather runs. Data dependency is an
// explicit release/acquire handshake: each gather CTA release-increments a
// counter after storing its partial; the finalize acquire-spins until all
// 32 arrive, then does a fixed-order reduction (rel_err 0) and resets the
// counter for the next graph replay.

#define NBLOCKS  32
#define NTHREADS 256

__device__ float g_partials[NBLOCKS];
__device__ int   g_done = 0;

__global__ __launch_bounds__(NTHREADS) void gather_kernel(
    const float* __restrict__ prob,
    const int* __restrict__ targets,
    const float* __restrict__ reward,
    int N, long long C)
{
    // Release the dependent finalize grid immediately: its launch + block
    // dispatch overlap our entire execution. Visibility of our results is
    // handled by the release/acquire counter below, not by PDL.
    cudaTriggerProgrammaticLaunchCompletion();

    int idx = blockIdx.x * blockDim.x + threadIdx.x;

    float v = 0.0f;
    if (idx < N) {
        int t = targets[idx];
        v = __ldg(&prob[(long long)idx * C + (long long)t]) * __ldg(&reward[idx]);
    }

    // warp reduce (5 shuffles)
    #pragma unroll
    for (int off = 16; off > 0; off >>= 1)
        v += __shfl_xor_sync(0xFFFFFFFFu, v, off);

    __shared__ float s_warp[NTHREADS / 32];
    const int lane = threadIdx.x & 31;
    const int wid  = threadIdx.x >> 5;
    if (lane == 0) s_warp[wid] = v;
    __syncthreads();

    if (threadIdx.x < 32) {
        float w = (lane < NTHREADS / 32) ? s_warp[lane] : 0.0f;
        #pragma unroll
        for (int off = 4; off > 0; off >>= 1)
            w += __shfl_xor_sync(0xFFFFFFFFu, w, off);
        if (lane == 0) {
            g_partials[blockIdx.x] = w;
            // release RMW: orders the partial store before the increment
            asm volatile("red.release.gpu.add.s32 [%0], %1;"
                         :: "l"(&g_done), "r"(1) : "memory");
        }
    }
}

__global__ __launch_bounds__(32) void finalize_kernel(
    float* __restrict__ out, float neg_inv_n)
{
    // Released early by the gather's entry trigger; spin until all 32
    // CTAs have release-incremented the counter.
    int c;
    do {
        asm volatile("ld.acquire.gpu.s32 %0, [%1];"
                     : "=r"(c) : "l"(&g_done) : "memory");
    } while (c < NBLOCKS);

    float v = g_partials[threadIdx.x];          // 32 partials, 1 warp
    #pragma unroll
    for (int off = 16; off > 0; off >>= 1)
        v += __shfl_xor_sync(0xFFFFFFFFu, v, off);

    if (threadIdx.x == 0) {
        out[0] = v * neg_inv_n;
        g_done = 0;   // reset for next graph replay (stream-order visible)
    }
}

extern "C" void kernel_launch(void* const* d_in, const int* in_sizes, int n_in,
                              void* d_out, int out_size)
{
    const float* prob    = (const float*)d_in[0];
    const int*   targets = (const int*)d_in[1];
    const float* reward  = (const float*)d_in[2];
    float*       out     = (float*)d_out;

    const int N = in_sizes[2];                       // 8192
    const long long C = (long long)in_sizes[0] / N;  // 32000

    gather_kernel<<<NBLOCKS, NTHREADS>>>(prob, targets, reward, N, C);

    cudaLaunchConfig_t cfg = {};
    cfg.gridDim  = dim3(1, 1, 1);
    cfg.blockDim = dim3(32, 1, 1);
    cfg.dynamicSmemBytes = 0;
    cfg.stream = 0;
    cudaLaunchAttribute attr;
    attr.id = cudaLaunchAttributeProgrammaticStreamSerialization;
    attr.val.programmaticStreamSerializationAllowed = 1;
    cfg.attrs = &attr;
    cfg.numAttrs = 1;

    float neg_inv_n = -1.0f / (float)N;
    cudaLaunchKernelEx(&cfg, finalize_kernel, out, neg_inv_n);
}